// round 14
// baseline (speedup 1.0000x reference)
#include <cuda_runtime.h>
#include <cuda_bf16.h>
#include <cstdint>
#include <cstddef>

#define DEVI __device__ __forceinline__

// ---------------- scratch (device globals; no allocation) ----------------
__device__ float g_V[8192 * 64];                 // stage-1 output
__device__ float g_H[(size_t)8192 * 4096];       // stage-2 output (tf32, K-permuted)
__device__ float g_Wnr[(size_t)4096 * 4096];     // Wn (tf32, K-permuted)

// K-permutation (within each 32-col block): stored position 4l+j holds
// original column j*8+l, so a thread's 4 per-ks fragment values are one float4.

// ---------------- helpers ----------------
DEVI float to_tf32(float x) {
    uint32_t u;
    asm("cvt.rna.tf32.f32 %0, %1;" : "=r"(u) : "f"(x));
    return __uint_as_float(u);
}
DEVI uint32_t smem_u32(const void* p) {
    uint32_t a;
    asm("{ .reg .u64 t; cvta.to.shared.u64 t, %1; cvt.u32.u64 %0, t; }" : "=r"(a) : "l"(p));
    return a;
}
DEVI void cp16(uint32_t saddr, const void* gaddr) {
    asm volatile("cp.async.cg.shared.global [%0], [%1], 16;" :: "r"(saddr), "l"(gaddr) : "memory");
}
DEVI void cp_commit() { asm volatile("cp.async.commit_group;" ::: "memory"); }
DEVI void cp_wait0()  { asm volatile("cp.async.wait_group 0;" ::: "memory"); }
DEVI void cp_wait1()  { asm volatile("cp.async.wait_group 1;" ::: "memory"); }

DEVI void mma8(float c[4], const uint32_t a[4], const uint32_t b[2]) {
    asm("mma.sync.aligned.m16n8k8.row.col.f32.tf32.tf32.f32 "
        "{%0,%1,%2,%3}, {%4,%5,%6,%7}, {%8,%9}, {%0,%1,%2,%3};\n"
        : "+f"(c[0]), "+f"(c[1]), "+f"(c[2]), "+f"(c[3])
        : "r"(a[0]), "r"(a[1]), "r"(a[2]), "r"(a[3]),
          "r"(b[0]), "r"(b[1]));
}

// ============================================================================
// Stage 3: out[8192,4096] = relu( H @ Wn^T + bn )
// mma.sync tf32. 128x256 CTA tile, 512 threads (16 warps, 64x32 warp tiles),
// K-tile 32, 3-stage cp.async pipeline, ONE barrier per k-tile.
// Operands pre-rounded + K-permuted; LDS.128 fragment loads.
// ============================================================================
static constexpr int S3_AS  = 128 * 32;                 // A stage floats (16 KB)
static constexpr int S3_BS  = 256 * 32;                 // B stage floats (32 KB)
static constexpr int S3_STG = S3_AS + S3_BS;            // 48 KB / stage
static constexpr int S3_SMEM = 3 * S3_STG * (int)sizeof(float);  // 147456 B

DEVI void s3_fill(float* stg,
                  const float* __restrict__ A, const float* __restrict__ B,
                  int bm, int bn, int k0, int tid)
{
    float* As = stg;
    float* Bs = stg + S3_AS;
#pragma unroll
    for (int i = 0; i < 2; ++i) {                   // A: 128 rows x 8 chunks = 1024
        const int ch = tid + (i << 9);
        const int r = ch >> 3, c4 = ch & 7;
        const int dst = r * 32 + ((c4 ^ ((r & 1) << 2)) << 2);
        cp16(smem_u32(As + dst), A + ((size_t)(bm * 128 + r) << 12) + k0 + (c4 << 2));
    }
#pragma unroll
    for (int i = 0; i < 4; ++i) {                   // B: 256 rows x 8 chunks = 2048
        const int ch = tid + (i << 9);
        const int r = ch >> 3, c4 = ch & 7;
        const int dst = r * 32 + ((c4 ^ ((r & 1) << 2)) << 2);
        cp16(smem_u32(Bs + dst), B + ((size_t)(bn * 256 + r) << 12) + k0 + (c4 << 2));
    }
}

__global__ void __launch_bounds__(512, 1)
gemm3_mma(const float* __restrict__ A,    // g_H   (tf32, permuted)
          const float* __restrict__ B,    // g_Wnr (tf32, permuted)
          const float* __restrict__ bias,
          float* __restrict__ C)
{
    constexpr int NK = 128;                         // 4096 / 32
    extern __shared__ float smem[];
    float* const stg[3] = { smem, smem + S3_STG, smem + 2 * S3_STG };

    const int tid  = threadIdx.x;
    const int lane = tid & 31;
    const int wid  = tid >> 5;
    const int g    = lane >> 2;
    const int tig  = lane & 3;
    const int wm   = (wid >> 3) * 64;               // warp row (0..1) * 64
    const int wn   = (wid & 7) * 32;                // warp col (0..7) * 32
    const int bn = blockIdx.x, bm = blockIdx.y;
    const int s4 = (g & 1) << 2;
    const int cL = ((tig    ) ^ s4) << 2;
    const int cH = ((tig + 4) ^ s4) << 2;

    float acc[4][4][4];
#pragma unroll
    for (int mt = 0; mt < 4; ++mt)
#pragma unroll
        for (int nt = 0; nt < 4; ++nt)
#pragma unroll
            for (int i = 0; i < 4; ++i) acc[mt][nt][i] = 0.f;

    s3_fill(stg[0], A, B, bm, bn, 0,  tid); cp_commit();
    s3_fill(stg[1], A, B, bm, bn, 32, tid); cp_commit();

    for (int kt = 0; kt < NK; ++kt) {
        if (kt == NK - 1) cp_wait0(); else cp_wait1();
        __syncthreads();                            // stage kt ready; all warps past kt-1

        const float* __restrict__ Ac = stg[kt % 3];
        const float* __restrict__ Bc = Ac + S3_AS;

        // B fragments resident: 4 nt x 2 float4
        float4 bv0[4], bv1[4];
#pragma unroll
        for (int nt = 0; nt < 4; ++nt) {
            const int rb = (wn + nt * 8 + g) * 32;
            bv0[nt] = *(const float4*)&Bc[rb + cL];
            bv1[nt] = *(const float4*)&Bc[rb + cH];
        }

#pragma unroll
        for (int mt = 0; mt < 4; ++mt) {
            const int r0 = (wm + mt * 16 + g) * 32;
            const int r1 = r0 + 8 * 32;
            const float4 a0 = *(const float4*)&Ac[r0 + cL];
            const float4 a1 = *(const float4*)&Ac[r1 + cL];
            const float4 a2 = *(const float4*)&Ac[r0 + cH];
            const float4 a3 = *(const float4*)&Ac[r1 + cH];
#pragma unroll
            for (int ks = 0; ks < 4; ++ks) {
                uint32_t af[4];
                af[0] = __float_as_uint(((const float*)&a0)[ks]);
                af[1] = __float_as_uint(((const float*)&a1)[ks]);
                af[2] = __float_as_uint(((const float*)&a2)[ks]);
                af[3] = __float_as_uint(((const float*)&a3)[ks]);
#pragma unroll
                for (int nt = 0; nt < 4; ++nt) {
                    uint32_t bf[2];
                    bf[0] = __float_as_uint(((const float*)&bv0[nt])[ks]);
                    bf[1] = __float_as_uint(((const float*)&bv1[nt])[ks]);
                    mma8(acc[mt][nt], af, bf);
                }
            }
        }

        // refill stage (kt+2)%3 — distinct from the two buffers in use; the
        // barrier above already guarantees no warp still reads it (last read kt-1)
        const int nt2 = kt + 2;
        if (nt2 < NK) {
            s3_fill(stg[nt2 % 3], A, B, bm, bn, nt2 * 32, tid);
            cp_commit();
        }
    }

    // epilogue: bias + relu
#pragma unroll
    for (int mt = 0; mt < 4; ++mt) {
#pragma unroll
        for (int nt = 0; nt < 4; ++nt) {
            const int m = bm * 128 + wm + mt * 16 + g;
            const int n = bn * 256 + wn + nt * 8 + 2 * tig;
            const float2 bb = *(const float2*)(bias + n);
            float2 v0, v1;
            v0.x = fmaxf(acc[mt][nt][0] + bb.x, 0.f);
            v0.y = fmaxf(acc[mt][nt][1] + bb.y, 0.f);
            v1.x = fmaxf(acc[mt][nt][2] + bb.x, 0.f);
            v1.y = fmaxf(acc[mt][nt][3] + bb.y, 0.f);
            *(float2*)(C + ((size_t)m << 12) + n)       = v0;
            *(float2*)(C + ((size_t)(m + 8) << 12) + n) = v1;
        }
    }
}

// ============================================================================
// Permute+round pass: Wn -> g_Wnr (tf32, K-permuted within 32-col blocks)
// out[r][b*32 + 4l + j] = round(in[r][b*32 + j*8 + l])
// ============================================================================
__global__ void perm_round_kernel(const float* __restrict__ in, float* __restrict__ out)
{
    const int total = 4096 * 1024;
    for (int idx = blockIdx.x * blockDim.x + threadIdx.x; idx < total;
         idx += gridDim.x * blockDim.x) {
        const int l = idx & 7;
        const int b = (idx >> 3) & 127;
        const int r = idx >> 10;
        const float* src = in + ((size_t)r << 12) + b * 32 + l;
        float4 v;
        v.x = to_tf32(src[0]);
        v.y = to_tf32(src[8]);
        v.z = to_tf32(src[16]);
        v.w = to_tf32(src[24]);
        *(float4*)(out + ((size_t)r << 12) + b * 32 + 4 * l) = v;
    }
}

// ============================================================================
// V init: V[m][n] = bv[n]  (8192 x 64)
// ============================================================================
__global__ void init_bias_kernel(float4* __restrict__ V, const float4* __restrict__ bv)
{
    for (int i = blockIdx.x * blockDim.x + threadIdx.x; i < 131072; i += gridDim.x * blockDim.x)
        V[i] = bv[i & 15];
}

// ============================================================================
// Stages 1-2: mma.sync tf32 GEMM
// EPI: 2 = +bias +resid, round, K-PERMUTED output (stage 2 -> g_H)
//      3 = split-K atomicAdd (stage 1)
// ============================================================================
DEVI void mma8s(float c[4], const uint32_t a[4], const uint32_t b[2]) { mma8(c, a, b); }

template <int BM, int BN, int EPI>
__global__ void __launch_bounds__(256, 1)
gemm_tf32_kernel(const float* __restrict__ A,
                 const float* __restrict__ B,
                 const float* __restrict__ bias,
                 const float* __restrict__ resid,
                 float* __restrict__ C,
                 int M, int N, int Klen, int ldk)
{
    constexpr int MT = BM / 32;
    constexpr int NT = BN / 32;
    constexpr int LD = 36;

    extern __shared__ float smemf[];
    float* const As0 = smemf;
    float* const As1 = smemf + BM * LD;
    float* const Bs0 = smemf + 2 * BM * LD;
    float* const Bs1 = smemf + 2 * BM * LD + BN * LD;
    float* const Asb[2] = { As0, As1 };
    float* const Bsb[2] = { Bs0, Bs1 };

    const int tid  = threadIdx.x;
    const int lane = tid & 31;
    const int wid  = tid >> 5;
    const int g    = lane >> 2;
    const int tig  = lane & 3;

    const int wm = (wid >> 2) * (BM / 2);
    const int wn = (wid & 3) * (BN / 4);

    const size_t koff = (size_t)blockIdx.z * Klen;
    const float* Ab = A + (size_t)blockIdx.y * BM * ldk + koff;
    const float* Bb = B + (size_t)blockIdx.x * BN * ldk + koff;

    const int lr = tid >> 3;
    const int lc = (tid & 7) * 4;

    float4 ra[MT], rb[NT];
    float acc[MT][NT][4];
#pragma unroll
    for (int mt = 0; mt < MT; ++mt)
#pragma unroll
        for (int nt = 0; nt < NT; ++nt)
#pragma unroll
            for (int i = 0; i < 4; ++i) acc[mt][nt][i] = 0.f;

    const int ktiles = Klen >> 5;

#pragma unroll
    for (int i = 0; i < MT; ++i)
        ra[i] = *(const float4*)(Ab + (size_t)(lr + 32 * i) * ldk + lc);
#pragma unroll
    for (int i = 0; i < NT; ++i)
        rb[i] = *(const float4*)(Bb + (size_t)(lr + 32 * i) * ldk + lc);
#pragma unroll
    for (int i = 0; i < MT; ++i) {
        float4 t = ra[i];
        t.x = to_tf32(t.x); t.y = to_tf32(t.y); t.z = to_tf32(t.z); t.w = to_tf32(t.w);
        *(float4*)&As0[(lr + 32 * i) * LD + lc] = t;
    }
#pragma unroll
    for (int i = 0; i < NT; ++i) {
        float4 t = rb[i];
        t.x = to_tf32(t.x); t.y = to_tf32(t.y); t.z = to_tf32(t.z); t.w = to_tf32(t.w);
        *(float4*)&Bs0[(lr + 32 * i) * LD + lc] = t;
    }
    __syncthreads();

    for (int kt = 0; kt < ktiles; ++kt) {
        const int cur = kt & 1;
        const bool more = (kt + 1) < ktiles;

        if (more) {
            const int ko = (kt + 1) * 32;
#pragma unroll
            for (int i = 0; i < MT; ++i)
                ra[i] = *(const float4*)(Ab + (size_t)(lr + 32 * i) * ldk + ko + lc);
#pragma unroll
            for (int i = 0; i < NT; ++i)
                rb[i] = *(const float4*)(Bb + (size_t)(lr + 32 * i) * ldk + ko + lc);
        }

        const float* __restrict__ Ac = Asb[cur];
        const float* __restrict__ Bc = Bsb[cur];
#pragma unroll
        for (int ks = 0; ks < 4; ++ks) {
            uint32_t af[MT][4];
            uint32_t bf[NT][2];
            const int c0 = ks * 8 + tig;
#pragma unroll
            for (int mt = 0; mt < MT; ++mt) {
                const int r0 = wm + mt * 16 + g;
                af[mt][0] = __float_as_uint(Ac[r0 * LD + c0]);
                af[mt][1] = __float_as_uint(Ac[(r0 + 8) * LD + c0]);
                af[mt][2] = __float_as_uint(Ac[r0 * LD + c0 + 4]);
                af[mt][3] = __float_as_uint(Ac[(r0 + 8) * LD + c0 + 4]);
            }
#pragma unroll
            for (int nt = 0; nt < NT; ++nt) {
                const int r0 = wn + nt * 8 + g;
                bf[nt][0] = __float_as_uint(Bc[r0 * LD + c0]);
                bf[nt][1] = __float_as_uint(Bc[r0 * LD + c0 + 4]);
            }
#pragma unroll
            for (int mt = 0; mt < MT; ++mt)
#pragma unroll
                for (int nt = 0; nt < NT; ++nt)
                    mma8s(acc[mt][nt], af[mt], bf[nt]);
        }

        if (more) {
            float* const An = Asb[cur ^ 1];
            float* const Bn = Bsb[cur ^ 1];
#pragma unroll
            for (int i = 0; i < MT; ++i) {
                float4 t = ra[i];
                t.x = to_tf32(t.x); t.y = to_tf32(t.y); t.z = to_tf32(t.z); t.w = to_tf32(t.w);
                *(float4*)&An[(lr + 32 * i) * LD + lc] = t;
            }
#pragma unroll
            for (int i = 0; i < NT; ++i) {
                float4 t = rb[i];
                t.x = to_tf32(t.x); t.y = to_tf32(t.y); t.z = to_tf32(t.z); t.w = to_tf32(t.w);
                *(float4*)&Bn[(lr + 32 * i) * LD + lc] = t;
            }
        }
        __syncthreads();
    }

    const int m0 = blockIdx.y * BM + wm;
    const int n0 = blockIdx.x * BN + wn;

    if (EPI == 2) {
        // K-permuted write: element across nt forms one float4
#pragma unroll
        for (int mt = 0; mt < MT; ++mt) {
            const int m = m0 + mt * 16 + g;
            float4 e0, e1, e2, e3;
#pragma unroll
            for (int nt = 0; nt < NT; ++nt) {
                const int nc = n0 + nt * 8 + 2 * tig;
                const float b0 = bias[nc], b1 = bias[nc + 1];
                const float2 r0 = *(const float2*)(resid + (size_t)m * N + nc);
                const float2 r1 = *(const float2*)(resid + (size_t)(m + 8) * N + nc);
                ((float*)&e0)[nt] = to_tf32(acc[mt][nt][0] + b0 + r0.x);
                ((float*)&e1)[nt] = to_tf32(acc[mt][nt][1] + b1 + r0.y);
                ((float*)&e2)[nt] = to_tf32(acc[mt][nt][2] + b0 + r1.x);
                ((float*)&e3)[nt] = to_tf32(acc[mt][nt][3] + b1 + r1.y);
            }
            float* c0p = C + (size_t)m * N + n0 + 8 * tig;
            float* c1p = C + (size_t)(m + 8) * N + n0 + 8 * tig;
            *(float4*)(c0p)     = e0;
            *(float4*)(c0p + 4) = e1;
            *(float4*)(c1p)     = e2;
            *(float4*)(c1p + 4) = e3;
        }
    } else {
#pragma unroll
        for (int mt = 0; mt < MT; ++mt) {
#pragma unroll
            for (int nt = 0; nt < NT; ++nt) {
                const int m = m0 + mt * 16 + g;
                const int n = n0 + nt * 8 + 2 * tig;
                atomicAdd(C + (size_t)m * N + n,           acc[mt][nt][0]);
                atomicAdd(C + (size_t)m * N + n + 1,       acc[mt][nt][1]);
                atomicAdd(C + (size_t)(m + 8) * N + n,     acc[mt][nt][2]);
                atomicAdd(C + (size_t)(m + 8) * N + n + 1, acc[mt][nt][3]);
            }
        }
    }
}

// ============================================================================
// launch
// Inputs (metadata order): x, Wq, bq, Wk, bk, Wv, bv, Wo, bo, Wn, bn
// Singleton softmax => attended == v; Wq/bq/Wk/bk dead.
// ============================================================================
extern "C" void kernel_launch(void* const* d_in, const int* in_sizes, int n_in,
                              void* d_out, int out_size)
{
    const float* x  = (const float*)d_in[0];
    const float* Wv = (const float*)d_in[5];
    const float* bv = (const float*)d_in[6];
    const float* Wo = (const float*)d_in[7];
    const float* bo = (const float*)d_in[8];
    const float* Wn = (const float*)d_in[9];
    const float* bn = (const float*)d_in[10];
    float* out = (float*)d_out;

    float *V = nullptr, *H = nullptr, *Wnr = nullptr;
    cudaGetSymbolAddress((void**)&V,   g_V);
    cudaGetSymbolAddress((void**)&H,   g_H);
    cudaGetSymbolAddress((void**)&Wnr, g_Wnr);

    constexpr int SM64  = 2 * (64 + 64)   * 36 * (int)sizeof(float);
    constexpr int SM128 = 2 * (128 + 128) * 36 * (int)sizeof(float);

    cudaFuncSetAttribute(gemm_tf32_kernel<64, 64, 3>,
                         cudaFuncAttributeMaxDynamicSharedMemorySize, SM64);
    cudaFuncSetAttribute(gemm_tf32_kernel<128, 128, 2>,
                         cudaFuncAttributeMaxDynamicSharedMemorySize, SM128);
    cudaFuncSetAttribute(gemm3_mma,
                         cudaFuncAttributeMaxDynamicSharedMemorySize, S3_SMEM);

    // Wn -> tf32-rounded, K-permuted copy
    perm_round_kernel<<<4096, 256>>>(Wn, Wnr);

    // Stage 1: V = bv ; V += x @ Wv^T  (split-K x4, atomicAdd)
    init_bias_kernel<<<512, 256>>>((float4*)V, (const float4*)bv);
    gemm_tf32_kernel<64, 64, 3><<<dim3(1, 128, 4), 256, SM64>>>(
        x, Wv, nullptr, nullptr, V, 8192, 64, 1024, 4096);

    // Stage 2: H = perm( round_tf32( V @ Wo^T + bo + x ) )
    gemm_tf32_kernel<128, 128, 2><<<dim3(32, 64, 1), 256, SM128>>>(
        V, Wo, bo, x, H, 8192, 4096, 64, 64);

    // Stage 3: out = relu(H @ Wn^T + bn) — 512 threads, 3-stage pipeline
    gemm3_mma<<<dim3(16, 64), 512, S3_SMEM>>>(H, Wnr, bn, out);
}

// round 15
// speedup vs baseline: 1.7198x; 1.7198x over previous
#include <cuda_runtime.h>
#include <cuda_fp16.h>
#include <cstdint>
#include <cstddef>

#define DEVI __device__ __forceinline__

// ---------------- scratch (device globals; no allocation) ----------------
__device__ float  g_V[8192 * 64];                  // stage-1 output (fp32)
__device__ __half g_Hh[(size_t)8192 * 4096];       // stage-2 output (fp16)
__device__ __half g_Wnh[(size_t)4096 * 4096];      // Wn (fp16)

// ---------------- helpers ----------------
DEVI float to_tf32(float x) {
    uint32_t u;
    asm("cvt.rna.tf32.f32 %0, %1;" : "=r"(u) : "f"(x));
    return __uint_as_float(u);
}
DEVI uint32_t smem_u32(const void* p) {
    uint32_t a;
    asm("{ .reg .u64 t; cvta.to.shared.u64 t, %1; cvt.u32.u64 %0, t; }" : "=r"(a) : "l"(p));
    return a;
}
DEVI void cp16(uint32_t saddr, const void* gaddr) {
    asm volatile("cp.async.cg.shared.global [%0], [%1], 16;" :: "r"(saddr), "l"(gaddr) : "memory");
}
DEVI void cp_commit() { asm volatile("cp.async.commit_group;" ::: "memory"); }
DEVI void cp_wait0()  { asm volatile("cp.async.wait_group 0;" ::: "memory"); }
DEVI void cp_wait1()  { asm volatile("cp.async.wait_group 1;" ::: "memory"); }

DEVI void mma8(float c[4], const uint32_t a[4], const uint32_t b[2]) {
    asm("mma.sync.aligned.m16n8k8.row.col.f32.tf32.tf32.f32 "
        "{%0,%1,%2,%3}, {%4,%5,%6,%7}, {%8,%9}, {%0,%1,%2,%3};\n"
        : "+f"(c[0]), "+f"(c[1]), "+f"(c[2]), "+f"(c[3])
        : "r"(a[0]), "r"(a[1]), "r"(a[2]), "r"(a[3]),
          "r"(b[0]), "r"(b[1]));
}
DEVI void mma16(float c[4], const uint32_t a[4], const uint32_t b[2]) {
    asm("mma.sync.aligned.m16n8k16.row.col.f32.f16.f16.f32 "
        "{%0,%1,%2,%3}, {%4,%5,%6,%7}, {%8,%9}, {%0,%1,%2,%3};\n"
        : "+f"(c[0]), "+f"(c[1]), "+f"(c[2]), "+f"(c[3])
        : "r"(a[0]), "r"(a[1]), "r"(a[2]), "r"(a[3]),
          "r"(b[0]), "r"(b[1]));
}

// ============================================================================
// Stage 3: out[8192,4096] = relu( Hh @ Wnh^T + bn )   (fp16 in, fp32 accum)
// mma.sync m16n8k16. 128x256 CTA tile, 256 threads, 64x64 warp tiles,
// K-tile 32 (2 k-steps), double-buffered cp.async. R12 structure.
// ============================================================================
static constexpr int S3_LDH = 40;                   // halves per smem row (80 B)
static constexpr int S3_AS  = 128 * S3_LDH;         // A stage halves
static constexpr int S3_BS  = 256 * S3_LDH;         // B stage halves
static constexpr int S3_STG = S3_AS + S3_BS;        // 15360 halves / stage
static constexpr int S3_SMEM = 2 * S3_STG * (int)sizeof(__half);   // 61440 B

DEVI void s3_fill(__half* st, const __half* __restrict__ A, const __half* __restrict__ B,
                  int bm, int bn, int k0, int tid)
{
    __half* As = st;
    __half* Bs = st + S3_AS;
#pragma unroll
    for (int i = 0; i < 2; ++i) {                   // A: 128 rows x 4 chunks = 512
        const int ch = tid + (i << 8);
        const int r = ch >> 2, c = ch & 3;
        cp16(smem_u32(As + r * S3_LDH + c * 8),
             A + ((size_t)(bm * 128 + r) << 12) + k0 + (c << 3));
    }
#pragma unroll
    for (int i = 0; i < 4; ++i) {                   // B: 256 rows x 4 chunks = 1024
        const int ch = tid + (i << 8);
        const int r = ch >> 2, c = ch & 3;
        cp16(smem_u32(Bs + r * S3_LDH + c * 8),
             B + ((size_t)(bn * 256 + r) << 12) + k0 + (c << 3));
    }
}

__global__ void __launch_bounds__(256, 1)
gemm3_fp16(const __half* __restrict__ A,    // g_Hh  [8192,4096]
           const __half* __restrict__ B,    // g_Wnh [4096,4096]
           const float* __restrict__ bias,
           float* __restrict__ C)
{
    constexpr int NK = 128;                         // 4096 / 32
    extern __shared__ __half smh[];
    __half* const stg[2] = { smh, smh + S3_STG };

    const int tid  = threadIdx.x;
    const int lane = tid & 31;
    const int wid  = tid >> 5;
    const int g    = lane >> 2;
    const int tig  = lane & 3;
    const int wm   = (wid >> 2) * 64;
    const int wn   = (wid & 3) * 64;
    const int bn = blockIdx.x, bm = blockIdx.y;

    float acc[4][8][4];
#pragma unroll
    for (int mt = 0; mt < 4; ++mt)
#pragma unroll
        for (int nt = 0; nt < 8; ++nt)
#pragma unroll
            for (int i = 0; i < 4; ++i) acc[mt][nt][i] = 0.f;

    s3_fill(stg[0], A, B, bm, bn, 0,  tid); cp_commit();
    s3_fill(stg[1], A, B, bm, bn, 32, tid); cp_commit();

    for (int kt = 0; kt < NK; ++kt) {
        const int s = kt & 1;
        if (kt == NK - 1) cp_wait0(); else cp_wait1();
        __syncthreads();

        const __half* __restrict__ Ac = stg[s];
        const __half* __restrict__ Bc = Ac + S3_AS;

#pragma unroll
        for (int ks = 0; ks < 2; ++ks) {
            const int kb = ks * 16 + 2 * tig;       // half offset of this thread's k-pair
            uint32_t af[4][4];
            uint32_t bf[8][2];
#pragma unroll
            for (int mt = 0; mt < 4; ++mt) {
                const int r0 = (wm + mt * 16 + g) * S3_LDH;
                const int r1 = r0 + 8 * S3_LDH;
                af[mt][0] = *(const uint32_t*)&Ac[r0 + kb];
                af[mt][1] = *(const uint32_t*)&Ac[r1 + kb];
                af[mt][2] = *(const uint32_t*)&Ac[r0 + kb + 8];
                af[mt][3] = *(const uint32_t*)&Ac[r1 + kb + 8];
            }
#pragma unroll
            for (int nt = 0; nt < 8; ++nt) {
                const int rb = (wn + nt * 8 + g) * S3_LDH;
                bf[nt][0] = *(const uint32_t*)&Bc[rb + kb];
                bf[nt][1] = *(const uint32_t*)&Bc[rb + kb + 8];
            }
#pragma unroll
            for (int mt = 0; mt < 4; ++mt)
#pragma unroll
                for (int nt = 0; nt < 8; ++nt)
                    mma16(acc[mt][nt], af[mt], bf[nt]);
        }

        __syncthreads();
        const int nt2 = kt + 2;
        if (nt2 < NK) {
            s3_fill(stg[s], A, B, bm, bn, nt2 * 32, tid);
            cp_commit();
        }
    }

    // epilogue: bias + relu
#pragma unroll
    for (int mt = 0; mt < 4; ++mt) {
#pragma unroll
        for (int nt = 0; nt < 8; ++nt) {
            const int m = bm * 128 + wm + mt * 16 + g;
            const int n = bn * 256 + wn + nt * 8 + 2 * tig;
            const float2 bb = *(const float2*)(bias + n);
            float2 v0, v1;
            v0.x = fmaxf(acc[mt][nt][0] + bb.x, 0.f);
            v0.y = fmaxf(acc[mt][nt][1] + bb.y, 0.f);
            v1.x = fmaxf(acc[mt][nt][2] + bb.x, 0.f);
            v1.y = fmaxf(acc[mt][nt][3] + bb.y, 0.f);
            *(float2*)(C + ((size_t)m << 12) + n)       = v0;
            *(float2*)(C + ((size_t)(m + 8) << 12) + n) = v1;
        }
    }
}

// ============================================================================
// fp32 -> fp16 conversion (Wn -> g_Wnh)
// ============================================================================
__global__ void f32_to_f16_kernel(const float2* __restrict__ in, __half2* __restrict__ out, int n2)
{
    for (int i = blockIdx.x * blockDim.x + threadIdx.x; i < n2; i += gridDim.x * blockDim.x) {
        const float2 v = in[i];
        out[i] = __floats2half2_rn(v.x, v.y);
    }
}

// ============================================================================
// V init: V[m][n] = bv[n]  (8192 x 64)
// ============================================================================
__global__ void init_bias_kernel(float4* __restrict__ V, const float4* __restrict__ bv)
{
    for (int i = blockIdx.x * blockDim.x + threadIdx.x; i < 131072; i += gridDim.x * blockDim.x)
        V[i] = bv[i & 15];
}

// ============================================================================
// Stages 1-2: mma.sync tf32 GEMM (proven)
// EPI: 3 = split-K atomicAdd (stage 1, C = fp32)
//      4 = +bias +resid, fp16 output (stage 2 -> g_Hh; C cast to __half*)
// ============================================================================
template <int BM, int BN, int EPI>
__global__ void __launch_bounds__(256, 1)
gemm_tf32_kernel(const float* __restrict__ A,
                 const float* __restrict__ B,
                 const float* __restrict__ bias,
                 const float* __restrict__ resid,
                 float* __restrict__ C,
                 int M, int N, int Klen, int ldk)
{
    constexpr int MT = BM / 32;
    constexpr int NT = BN / 32;
    constexpr int LD = 36;

    extern __shared__ float smemf[];
    float* const As0 = smemf;
    float* const As1 = smemf + BM * LD;
    float* const Bs0 = smemf + 2 * BM * LD;
    float* const Bs1 = smemf + 2 * BM * LD + BN * LD;
    float* const Asb[2] = { As0, As1 };
    float* const Bsb[2] = { Bs0, Bs1 };

    const int tid  = threadIdx.x;
    const int lane = tid & 31;
    const int wid  = tid >> 5;
    const int g    = lane >> 2;
    const int tig  = lane & 3;

    const int wm = (wid >> 2) * (BM / 2);
    const int wn = (wid & 3) * (BN / 4);

    const size_t koff = (size_t)blockIdx.z * Klen;
    const float* Ab = A + (size_t)blockIdx.y * BM * ldk + koff;
    const float* Bb = B + (size_t)blockIdx.x * BN * ldk + koff;

    const int lr = tid >> 3;
    const int lc = (tid & 7) * 4;

    float4 ra[MT], rb[NT];
    float acc[MT][NT][4];
#pragma unroll
    for (int mt = 0; mt < MT; ++mt)
#pragma unroll
        for (int nt = 0; nt < NT; ++nt)
#pragma unroll
            for (int i = 0; i < 4; ++i) acc[mt][nt][i] = 0.f;

    const int ktiles = Klen >> 5;

#pragma unroll
    for (int i = 0; i < MT; ++i)
        ra[i] = *(const float4*)(Ab + (size_t)(lr + 32 * i) * ldk + lc);
#pragma unroll
    for (int i = 0; i < NT; ++i)
        rb[i] = *(const float4*)(Bb + (size_t)(lr + 32 * i) * ldk + lc);
#pragma unroll
    for (int i = 0; i < MT; ++i) {
        float4 t = ra[i];
        t.x = to_tf32(t.x); t.y = to_tf32(t.y); t.z = to_tf32(t.z); t.w = to_tf32(t.w);
        *(float4*)&As0[(lr + 32 * i) * LD + lc] = t;
    }
#pragma unroll
    for (int i = 0; i < NT; ++i) {
        float4 t = rb[i];
        t.x = to_tf32(t.x); t.y = to_tf32(t.y); t.z = to_tf32(t.z); t.w = to_tf32(t.w);
        *(float4*)&Bs0[(lr + 32 * i) * LD + lc] = t;
    }
    __syncthreads();

    for (int kt = 0; kt < ktiles; ++kt) {
        const int cur = kt & 1;
        const bool more = (kt + 1) < ktiles;

        if (more) {
            const int ko = (kt + 1) * 32;
#pragma unroll
            for (int i = 0; i < MT; ++i)
                ra[i] = *(const float4*)(Ab + (size_t)(lr + 32 * i) * ldk + ko + lc);
#pragma unroll
            for (int i = 0; i < NT; ++i)
                rb[i] = *(const float4*)(Bb + (size_t)(lr + 32 * i) * ldk + ko + lc);
        }

        const float* __restrict__ Ac = Asb[cur];
        const float* __restrict__ Bc = Bsb[cur];
#pragma unroll
        for (int ks = 0; ks < 4; ++ks) {
            uint32_t af[MT][4];
            uint32_t bf[NT][2];
            const int c0 = ks * 8 + tig;
#pragma unroll
            for (int mt = 0; mt < MT; ++mt) {
                const int r0 = wm + mt * 16 + g;
                af[mt][0] = __float_as_uint(Ac[r0 * LD + c0]);
                af[mt][1] = __float_as_uint(Ac[(r0 + 8) * LD + c0]);
                af[mt][2] = __float_as_uint(Ac[r0 * LD + c0 + 4]);
                af[mt][3] = __float_as_uint(Ac[(r0 + 8) * LD + c0 + 4]);
            }
#pragma unroll
            for (int nt = 0; nt < NT; ++nt) {
                const int r0 = wn + nt * 8 + g;
                bf[nt][0] = __float_as_uint(Bc[r0 * LD + c0]);
                bf[nt][1] = __float_as_uint(Bc[r0 * LD + c0 + 4]);
            }
#pragma unroll
            for (int mt = 0; mt < MT; ++mt)
#pragma unroll
                for (int nt = 0; nt < NT; ++nt)
                    mma8(acc[mt][nt], af[mt], bf[nt]);
        }

        if (more) {
            float* const An = Asb[cur ^ 1];
            float* const Bn = Bsb[cur ^ 1];
#pragma unroll
            for (int i = 0; i < MT; ++i) {
                float4 t = ra[i];
                t.x = to_tf32(t.x); t.y = to_tf32(t.y); t.z = to_tf32(t.z); t.w = to_tf32(t.w);
                *(float4*)&An[(lr + 32 * i) * LD + lc] = t;
            }
#pragma unroll
            for (int i = 0; i < NT; ++i) {
                float4 t = rb[i];
                t.x = to_tf32(t.x); t.y = to_tf32(t.y); t.z = to_tf32(t.z); t.w = to_tf32(t.w);
                *(float4*)&Bn[(lr + 32 * i) * LD + lc] = t;
            }
        }
        __syncthreads();
    }

    const int m0 = blockIdx.y * BM + wm;
    const int n0 = blockIdx.x * BN + wn;

    if (EPI == 4) {
        __half2* const Ch = (__half2*)C;
#pragma unroll
        for (int mt = 0; mt < MT; ++mt) {
#pragma unroll
            for (int nt = 0; nt < NT; ++nt) {
                const int m = m0 + mt * 16 + g;
                const int n = n0 + nt * 8 + 2 * tig;
                const float2 bb = *(const float2*)(bias + n);
                const float2 r0 = *(const float2*)(resid + (size_t)m * N + n);
                const float2 r1 = *(const float2*)(resid + (size_t)(m + 8) * N + n);
                const float v0 = acc[mt][nt][0] + bb.x + r0.x;
                const float v1 = acc[mt][nt][1] + bb.y + r0.y;
                const float v2 = acc[mt][nt][2] + bb.x + r1.x;
                const float v3 = acc[mt][nt][3] + bb.y + r1.y;
                Ch[((size_t)m * N + n) >> 1]       = __floats2half2_rn(v0, v1);
                Ch[((size_t)(m + 8) * N + n) >> 1] = __floats2half2_rn(v2, v3);
            }
        }
    } else {
#pragma unroll
        for (int mt = 0; mt < MT; ++mt) {
#pragma unroll
            for (int nt = 0; nt < NT; ++nt) {
                const int m = m0 + mt * 16 + g;
                const int n = n0 + nt * 8 + 2 * tig;
                atomicAdd(C + (size_t)m * N + n,           acc[mt][nt][0]);
                atomicAdd(C + (size_t)m * N + n + 1,       acc[mt][nt][1]);
                atomicAdd(C + (size_t)(m + 8) * N + n,     acc[mt][nt][2]);
                atomicAdd(C + (size_t)(m + 8) * N + n + 1, acc[mt][nt][3]);
            }
        }
    }
}

// ============================================================================
// launch
// Inputs (metadata order): x, Wq, bq, Wk, bk, Wv, bv, Wo, bo, Wn, bn
// Singleton softmax => attended == v; Wq/bq/Wk/bk dead.
// ============================================================================
extern "C" void kernel_launch(void* const* d_in, const int* in_sizes, int n_in,
                              void* d_out, int out_size)
{
    const float* x  = (const float*)d_in[0];
    const float* Wv = (const float*)d_in[5];
    const float* bv = (const float*)d_in[6];
    const float* Wo = (const float*)d_in[7];
    const float* bo = (const float*)d_in[8];
    const float* Wn = (const float*)d_in[9];
    const float* bn = (const float*)d_in[10];
    float* out = (float*)d_out;

    float  *V = nullptr;
    __half *Hh = nullptr, *Wnh = nullptr;
    cudaGetSymbolAddress((void**)&V,   g_V);
    cudaGetSymbolAddress((void**)&Hh,  g_Hh);
    cudaGetSymbolAddress((void**)&Wnh, g_Wnh);

    constexpr int SM64  = 2 * (64 + 64)   * 36 * (int)sizeof(float);
    constexpr int SM128 = 2 * (128 + 128) * 36 * (int)sizeof(float);

    cudaFuncSetAttribute(gemm_tf32_kernel<64, 64, 3>,
                         cudaFuncAttributeMaxDynamicSharedMemorySize, SM64);
    cudaFuncSetAttribute(gemm_tf32_kernel<128, 128, 4>,
                         cudaFuncAttributeMaxDynamicSharedMemorySize, SM128);
    cudaFuncSetAttribute(gemm3_fp16,
                         cudaFuncAttributeMaxDynamicSharedMemorySize, S3_SMEM);

    // Wn -> fp16 copy
    f32_to_f16_kernel<<<4096, 256>>>((const float2*)Wn, (__half2*)Wnh, 4096 * 4096 / 2);

    // Stage 1: V = bv ; V += x @ Wv^T  (split-K x4, atomicAdd)
    init_bias_kernel<<<512, 256>>>((float4*)V, (const float4*)bv);
    gemm_tf32_kernel<64, 64, 3><<<dim3(1, 128, 4), 256, SM64>>>(
        x, Wv, nullptr, nullptr, V, 8192, 64, 1024, 4096);

    // Stage 2: Hh = fp16( V @ Wo^T + bo + x )
    gemm_tf32_kernel<128, 128, 4><<<dim3(32, 64, 1), 256, SM128>>>(
        V, Wo, bo, x, (float*)Hh, 8192, 4096, 64, 64);

    // Stage 3: out = relu(Hh @ Wnh^T + bn)  — fp16 m16n8k16
    gemm3_fp16<<<dim3(16, 64), 256, S3_SMEM>>>(Hh, Wnh, bn, out);
}

// round 16
// speedup vs baseline: 1.9921x; 1.1583x over previous
#include <cuda_runtime.h>
#include <cuda_fp16.h>
#include <cstdint>
#include <cstddef>

#define DEVI __device__ __forceinline__

// ---------------- scratch (device globals; no allocation) ----------------
__device__ float  g_V[8192 * 64];                  // stage-1 output (fp32)
__device__ __half g_Hh[(size_t)8192 * 4096];       // stage-2 output (fp16)
__device__ __half g_Wnh[(size_t)4096 * 4096];      // Wn (fp16)

// ---------------- helpers ----------------
DEVI float to_tf32(float x) {
    uint32_t u;
    asm("cvt.rna.tf32.f32 %0, %1;" : "=r"(u) : "f"(x));
    return __uint_as_float(u);
}
DEVI uint32_t smem_u32(const void* p) {
    uint32_t a;
    asm("{ .reg .u64 t; cvta.to.shared.u64 t, %1; cvt.u32.u64 %0, t; }" : "=r"(a) : "l"(p));
    return a;
}
DEVI void cp16(uint32_t saddr, const void* gaddr) {
    asm volatile("cp.async.cg.shared.global [%0], [%1], 16;" :: "r"(saddr), "l"(gaddr) : "memory");
}
DEVI void cp_commit() { asm volatile("cp.async.commit_group;" ::: "memory"); }
DEVI void cp_wait0()  { asm volatile("cp.async.wait_group 0;" ::: "memory"); }
DEVI void cp_wait1()  { asm volatile("cp.async.wait_group 1;" ::: "memory"); }

DEVI void mma8(float c[4], const uint32_t a[4], const uint32_t b[2]) {
    asm("mma.sync.aligned.m16n8k8.row.col.f32.tf32.tf32.f32 "
        "{%0,%1,%2,%3}, {%4,%5,%6,%7}, {%8,%9}, {%0,%1,%2,%3};\n"
        : "+f"(c[0]), "+f"(c[1]), "+f"(c[2]), "+f"(c[3])
        : "r"(a[0]), "r"(a[1]), "r"(a[2]), "r"(a[3]),
          "r"(b[0]), "r"(b[1]));
}
DEVI void mma16(float c[4], const uint32_t a[4], const uint32_t b[2]) {
    asm("mma.sync.aligned.m16n8k16.row.col.f32.f16.f16.f32 "
        "{%0,%1,%2,%3}, {%4,%5,%6,%7}, {%8,%9}, {%0,%1,%2,%3};\n"
        : "+f"(c[0]), "+f"(c[1]), "+f"(c[2]), "+f"(c[3])
        : "r"(a[0]), "r"(a[1]), "r"(a[2]), "r"(a[3]),
          "r"(b[0]), "r"(b[1]));
}

// ============================================================================
// Stage 3: out[8192,4096] = relu( Hh @ Wnh^T + bn )   (fp16 in, fp32 accum)
// mma.sync m16n8k16. 128x256 CTA tile, 256 threads, 64x64 warp tiles.
// K-tile 64 (4 k-steps), 3-stage cp.async pipeline, ONE barrier per k-tile,
// fills issued BEFORE compute so DRAM latency hides under HMMA.
// ============================================================================
static constexpr int S3_LDH = 72;                   // halves per smem row (144 B)
static constexpr int S3_AS  = 128 * S3_LDH;         // A stage halves (9216)
static constexpr int S3_BS  = 256 * S3_LDH;         // B stage halves (18432)
static constexpr int S3_STG = S3_AS + S3_BS;        // 27648 halves / stage
static constexpr int S3_SMEM = 3 * S3_STG * (int)sizeof(__half);   // 165888 B

DEVI void s3_fill(__half* st, const __half* __restrict__ A, const __half* __restrict__ B,
                  int bm, int bn, int k0, int tid)
{
    __half* As = st;
    __half* Bs = st + S3_AS;
#pragma unroll
    for (int i = 0; i < 4; ++i) {                   // A: 128 rows x 8 chunks = 1024
        const int ch = tid + (i << 8);
        const int r = ch >> 3, c = ch & 7;
        cp16(smem_u32(As + r * S3_LDH + c * 8),
             A + ((size_t)(bm * 128 + r) << 12) + k0 + (c << 3));
    }
#pragma unroll
    for (int i = 0; i < 8; ++i) {                   // B: 256 rows x 8 chunks = 2048
        const int ch = tid + (i << 8);
        const int r = ch >> 3, c = ch & 7;
        cp16(smem_u32(Bs + r * S3_LDH + c * 8),
             B + ((size_t)(bn * 256 + r) << 12) + k0 + (c << 3));
    }
}

__global__ void __launch_bounds__(256, 1)
gemm3_fp16(const __half* __restrict__ A,    // g_Hh  [8192,4096]
           const __half* __restrict__ B,    // g_Wnh [4096,4096]
           const float* __restrict__ bias,
           float* __restrict__ C)
{
    constexpr int NK = 64;                          // 4096 / 64
    extern __shared__ __half smh[];
    __half* const stg[3] = { smh, smh + S3_STG, smh + 2 * S3_STG };

    const int tid  = threadIdx.x;
    const int lane = tid & 31;
    const int wid  = tid >> 5;
    const int g    = lane >> 2;
    const int tig  = lane & 3;
    const int wm   = (wid >> 2) * 64;
    const int wn   = (wid & 3) * 64;
    const int bn = blockIdx.x, bm = blockIdx.y;

    float acc[4][8][4];
#pragma unroll
    for (int mt = 0; mt < 4; ++mt)
#pragma unroll
        for (int nt = 0; nt < 8; ++nt)
#pragma unroll
            for (int i = 0; i < 4; ++i) acc[mt][nt][i] = 0.f;

    s3_fill(stg[0], A, B, bm, bn, 0,  tid); cp_commit();
    s3_fill(stg[1], A, B, bm, bn, 64, tid); cp_commit();

    for (int kt = 0; kt < NK; ++kt) {
        if (kt == NK - 1) cp_wait0(); else cp_wait1();
        __syncthreads();
        // Barrier proves: stage kt ready in all threads, and every warp is done
        // computing kt-1 -> buffer (kt+2)%3 == (kt-1)%3 is free to refill.

        const int nt2 = kt + 2;
        if (nt2 < NK) {
            s3_fill(stg[nt2 % 3], A, B, bm, bn, nt2 * 64, tid);
            cp_commit();
        }

        const __half* __restrict__ Ac = stg[kt % 3];
        const __half* __restrict__ Bc = Ac + S3_AS;

#pragma unroll
        for (int ks = 0; ks < 4; ++ks) {
            const int kb = ks * 16 + 2 * tig;
            uint32_t af[4][4];
            uint32_t bf[8][2];
#pragma unroll
            for (int mt = 0; mt < 4; ++mt) {
                const int r0 = (wm + mt * 16 + g) * S3_LDH;
                const int r1 = r0 + 8 * S3_LDH;
                af[mt][0] = *(const uint32_t*)&Ac[r0 + kb];
                af[mt][1] = *(const uint32_t*)&Ac[r1 + kb];
                af[mt][2] = *(const uint32_t*)&Ac[r0 + kb + 8];
                af[mt][3] = *(const uint32_t*)&Ac[r1 + kb + 8];
            }
#pragma unroll
            for (int nt = 0; nt < 8; ++nt) {
                const int rb = (wn + nt * 8 + g) * S3_LDH;
                bf[nt][0] = *(const uint32_t*)&Bc[rb + kb];
                bf[nt][1] = *(const uint32_t*)&Bc[rb + kb + 8];
            }
#pragma unroll
            for (int mt = 0; mt < 4; ++mt)
#pragma unroll
                for (int nt = 0; nt < 8; ++nt)
                    mma16(acc[mt][nt], af[mt], bf[nt]);
        }
    }

    // epilogue: bias + relu
#pragma unroll
    for (int mt = 0; mt < 4; ++mt) {
#pragma unroll
        for (int nt = 0; nt < 8; ++nt) {
            const int m = bm * 128 + wm + mt * 16 + g;
            const int n = bn * 256 + wn + nt * 8 + 2 * tig;
            const float2 bb = *(const float2*)(bias + n);
            float2 v0, v1;
            v0.x = fmaxf(acc[mt][nt][0] + bb.x, 0.f);
            v0.y = fmaxf(acc[mt][nt][1] + bb.y, 0.f);
            v1.x = fmaxf(acc[mt][nt][2] + bb.x, 0.f);
            v1.y = fmaxf(acc[mt][nt][3] + bb.y, 0.f);
            *(float2*)(C + ((size_t)m << 12) + n)       = v0;
            *(float2*)(C + ((size_t)(m + 8) << 12) + n) = v1;
        }
    }
}

// ============================================================================
// fp32 -> fp16 conversion (Wn -> g_Wnh)
// ============================================================================
__global__ void f32_to_f16_kernel(const float2* __restrict__ in, __half2* __restrict__ out, int n2)
{
    for (int i = blockIdx.x * blockDim.x + threadIdx.x; i < n2; i += gridDim.x * blockDim.x) {
        const float2 v = in[i];
        out[i] = __floats2half2_rn(v.x, v.y);
    }
}

// ============================================================================
// V init: V[m][n] = bv[n]  (8192 x 64)
// ============================================================================
__global__ void init_bias_kernel(float4* __restrict__ V, const float4* __restrict__ bv)
{
    for (int i = blockIdx.x * blockDim.x + threadIdx.x; i < 131072; i += gridDim.x * blockDim.x)
        V[i] = bv[i & 15];
}

// ============================================================================
// Stages 1-2: mma.sync tf32 GEMM (proven)
// EPI: 3 = split-K atomicAdd (stage 1, C = fp32)
//      4 = +bias +resid, fp16 output (stage 2 -> g_Hh; C cast to __half*)
// ============================================================================
template <int BM, int BN, int EPI>
__global__ void __launch_bounds__(256, 1)
gemm_tf32_kernel(const float* __restrict__ A,
                 const float* __restrict__ B,
                 const float* __restrict__ bias,
                 const float* __restrict__ resid,
                 float* __restrict__ C,
                 int M, int N, int Klen, int ldk)
{
    constexpr int MT = BM / 32;
    constexpr int NT = BN / 32;
    constexpr int LD = 36;

    extern __shared__ float smemf[];
    float* const As0 = smemf;
    float* const As1 = smemf + BM * LD;
    float* const Bs0 = smemf + 2 * BM * LD;
    float* const Bs1 = smemf + 2 * BM * LD + BN * LD;
    float* const Asb[2] = { As0, As1 };
    float* const Bsb[2] = { Bs0, Bs1 };

    const int tid  = threadIdx.x;
    const int lane = tid & 31;
    const int wid  = tid >> 5;
    const int g    = lane >> 2;
    const int tig  = lane & 3;

    const int wm = (wid >> 2) * (BM / 2);
    const int wn = (wid & 3) * (BN / 4);

    const size_t koff = (size_t)blockIdx.z * Klen;
    const float* Ab = A + (size_t)blockIdx.y * BM * ldk + koff;
    const float* Bb = B + (size_t)blockIdx.x * BN * ldk + koff;

    const int lr = tid >> 3;
    const int lc = (tid & 7) * 4;

    float4 ra[MT], rb[NT];
    float acc[MT][NT][4];
#pragma unroll
    for (int mt = 0; mt < MT; ++mt)
#pragma unroll
        for (int nt = 0; nt < NT; ++nt)
#pragma unroll
            for (int i = 0; i < 4; ++i) acc[mt][nt][i] = 0.f;

    const int ktiles = Klen >> 5;

#pragma unroll
    for (int i = 0; i < MT; ++i)
        ra[i] = *(const float4*)(Ab + (size_t)(lr + 32 * i) * ldk + lc);
#pragma unroll
    for (int i = 0; i < NT; ++i)
        rb[i] = *(const float4*)(Bb + (size_t)(lr + 32 * i) * ldk + lc);
#pragma unroll
    for (int i = 0; i < MT; ++i) {
        float4 t = ra[i];
        t.x = to_tf32(t.x); t.y = to_tf32(t.y); t.z = to_tf32(t.z); t.w = to_tf32(t.w);
        *(float4*)&As0[(lr + 32 * i) * LD + lc] = t;
    }
#pragma unroll
    for (int i = 0; i < NT; ++i) {
        float4 t = rb[i];
        t.x = to_tf32(t.x); t.y = to_tf32(t.y); t.z = to_tf32(t.z); t.w = to_tf32(t.w);
        *(float4*)&Bs0[(lr + 32 * i) * LD + lc] = t;
    }
    __syncthreads();

    for (int kt = 0; kt < ktiles; ++kt) {
        const int cur = kt & 1;
        const bool more = (kt + 1) < ktiles;

        if (more) {
            const int ko = (kt + 1) * 32;
#pragma unroll
            for (int i = 0; i < MT; ++i)
                ra[i] = *(const float4*)(Ab + (size_t)(lr + 32 * i) * ldk + ko + lc);
#pragma unroll
            for (int i = 0; i < NT; ++i)
                rb[i] = *(const float4*)(Bb + (size_t)(lr + 32 * i) * ldk + ko + lc);
        }

        const float* __restrict__ Ac = Asb[cur];
        const float* __restrict__ Bc = Bsb[cur];
#pragma unroll
        for (int ks = 0; ks < 4; ++ks) {
            uint32_t af[MT][4];
            uint32_t bf[NT][2];
            const int c0 = ks * 8 + tig;
#pragma unroll
            for (int mt = 0; mt < MT; ++mt) {
                const int r0 = wm + mt * 16 + g;
                af[mt][0] = __float_as_uint(Ac[r0 * LD + c0]);
                af[mt][1] = __float_as_uint(Ac[(r0 + 8) * LD + c0]);
                af[mt][2] = __float_as_uint(Ac[r0 * LD + c0 + 4]);
                af[mt][3] = __float_as_uint(Ac[(r0 + 8) * LD + c0 + 4]);
            }
#pragma unroll
            for (int nt = 0; nt < NT; ++nt) {
                const int r0 = wn + nt * 8 + g;
                bf[nt][0] = __float_as_uint(Bc[r0 * LD + c0]);
                bf[nt][1] = __float_as_uint(Bc[r0 * LD + c0 + 4]);
            }
#pragma unroll
            for (int mt = 0; mt < MT; ++mt)
#pragma unroll
                for (int nt = 0; nt < NT; ++nt)
                    mma8(acc[mt][nt], af[mt], bf[nt]);
        }

        if (more) {
            float* const An = Asb[cur ^ 1];
            float* const Bn = Bsb[cur ^ 1];
#pragma unroll
            for (int i = 0; i < MT; ++i) {
                float4 t = ra[i];
                t.x = to_tf32(t.x); t.y = to_tf32(t.y); t.z = to_tf32(t.z); t.w = to_tf32(t.w);
                *(float4*)&An[(lr + 32 * i) * LD + lc] = t;
            }
#pragma unroll
            for (int i = 0; i < NT; ++i) {
                float4 t = rb[i];
                t.x = to_tf32(t.x); t.y = to_tf32(t.y); t.z = to_tf32(t.z); t.w = to_tf32(t.w);
                *(float4*)&Bn[(lr + 32 * i) * LD + lc] = t;
            }
        }
        __syncthreads();
    }

    const int m0 = blockIdx.y * BM + wm;
    const int n0 = blockIdx.x * BN + wn;

    if (EPI == 4) {
        __half2* const Ch = (__half2*)C;
#pragma unroll
        for (int mt = 0; mt < MT; ++mt) {
#pragma unroll
            for (int nt = 0; nt < NT; ++nt) {
                const int m = m0 + mt * 16 + g;
                const int n = n0 + nt * 8 + 2 * tig;
                const float2 bb = *(const float2*)(bias + n);
                const float2 r0 = *(const float2*)(resid + (size_t)m * N + n);
                const float2 r1 = *(const float2*)(resid + (size_t)(m + 8) * N + n);
                const float v0 = acc[mt][nt][0] + bb.x + r0.x;
                const float v1 = acc[mt][nt][1] + bb.y + r0.y;
                const float v2 = acc[mt][nt][2] + bb.x + r1.x;
                const float v3 = acc[mt][nt][3] + bb.y + r1.y;
                Ch[((size_t)m * N + n) >> 1]       = __floats2half2_rn(v0, v1);
                Ch[((size_t)(m + 8) * N + n) >> 1] = __floats2half2_rn(v2, v3);
            }
        }
    } else {
#pragma unroll
        for (int mt = 0; mt < MT; ++mt) {
#pragma unroll
            for (int nt = 0; nt < NT; ++nt) {
                const int m = m0 + mt * 16 + g;
                const int n = n0 + nt * 8 + 2 * tig;
                atomicAdd(C + (size_t)m * N + n,           acc[mt][nt][0]);
                atomicAdd(C + (size_t)m * N + n + 1,       acc[mt][nt][1]);
                atomicAdd(C + (size_t)(m + 8) * N + n,     acc[mt][nt][2]);
                atomicAdd(C + (size_t)(m + 8) * N + n + 1, acc[mt][nt][3]);
            }
        }
    }
}

// ============================================================================
// launch
// Inputs (metadata order): x, Wq, bq, Wk, bk, Wv, bv, Wo, bo, Wn, bn
// Singleton softmax => attended == v; Wq/bq/Wk/bk dead.
// ============================================================================
extern "C" void kernel_launch(void* const* d_in, const int* in_sizes, int n_in,
                              void* d_out, int out_size)
{
    const float* x  = (const float*)d_in[0];
    const float* Wv = (const float*)d_in[5];
    const float* bv = (const float*)d_in[6];
    const float* Wo = (const float*)d_in[7];
    const float* bo = (const float*)d_in[8];
    const float* Wn = (const float*)d_in[9];
    const float* bn = (const float*)d_in[10];
    float* out = (float*)d_out;

    float  *V = nullptr;
    __half *Hh = nullptr, *Wnh = nullptr;
    cudaGetSymbolAddress((void**)&V,   g_V);
    cudaGetSymbolAddress((void**)&Hh,  g_Hh);
    cudaGetSymbolAddress((void**)&Wnh, g_Wnh);

    constexpr int SM64  = 2 * (64 + 64)   * 36 * (int)sizeof(float);
    constexpr int SM128 = 2 * (128 + 128) * 36 * (int)sizeof(float);

    cudaFuncSetAttribute(gemm_tf32_kernel<64, 64, 3>,
                         cudaFuncAttributeMaxDynamicSharedMemorySize, SM64);
    cudaFuncSetAttribute(gemm_tf32_kernel<128, 128, 4>,
                         cudaFuncAttributeMaxDynamicSharedMemorySize, SM128);
    cudaFuncSetAttribute(gemm3_fp16,
                         cudaFuncAttributeMaxDynamicSharedMemorySize, S3_SMEM);

    // Wn -> fp16 copy
    f32_to_f16_kernel<<<4096, 256>>>((const float2*)Wn, (__half2*)Wnh, 4096 * 4096 / 2);

    // Stage 1: V = bv ; V += x @ Wv^T  (split-K x4, atomicAdd)
    init_bias_kernel<<<512, 256>>>((float4*)V, (const float4*)bv);
    gemm_tf32_kernel<64, 64, 3><<<dim3(1, 128, 4), 256, SM64>>>(
        x, Wv, nullptr, nullptr, V, 8192, 64, 1024, 4096);

    // Stage 2: Hh = fp16( V @ Wo^T + bo + x )
    gemm_tf32_kernel<128, 128, 4><<<dim3(32, 64, 1), 256, SM128>>>(
        V, Wo, bo, x, (float*)Hh, 8192, 4096, 64, 64);

    // Stage 3: out = relu(Hh @ Wnh^T + bn) — K-tile 64, 3-stage, 1 barrier/iter
    gemm3_fp16<<<dim3(16, 64), 256, S3_SMEM>>>(Hh, Wnh, bn, out);
}

// round 17
// speedup vs baseline: 2.3647x; 1.1870x over previous
#include <cuda_runtime.h>
#include <cuda_fp16.h>
#include <cstdint>
#include <cstddef>

#define DEVI __device__ __forceinline__

// ---------------- scratch (device globals; no allocation) ----------------
__device__ float  g_V[8192 * 64];                  // stage-1 output (fp32)
__device__ __half g_Hh[(size_t)8192 * 4096];       // stage-2 output (fp16)
__device__ __half g_Wnh[(size_t)4096 * 4096];      // Wn (fp16)

// ---------------- helpers ----------------
DEVI float to_tf32(float x) {
    uint32_t u;
    asm("cvt.rna.tf32.f32 %0, %1;" : "=r"(u) : "f"(x));
    return __uint_as_float(u);
}
DEVI uint32_t smem_u32(const void* p) {
    uint32_t a;
    asm("{ .reg .u64 t; cvta.to.shared.u64 t, %1; cvt.u32.u64 %0, t; }" : "=r"(a) : "l"(p));
    return a;
}
DEVI void cp16(uint32_t saddr, const void* gaddr) {
    asm volatile("cp.async.cg.shared.global [%0], [%1], 16;" :: "r"(saddr), "l"(gaddr) : "memory");
}
DEVI void cp_commit() { asm volatile("cp.async.commit_group;" ::: "memory"); }
DEVI void cp_wait0()  { asm volatile("cp.async.wait_group 0;" ::: "memory"); }
DEVI void cp_wait1()  { asm volatile("cp.async.wait_group 1;" ::: "memory"); }

DEVI void mma8(float c[4], const uint32_t a[4], const uint32_t b[2]) {
    asm("mma.sync.aligned.m16n8k8.row.col.f32.tf32.tf32.f32 "
        "{%0,%1,%2,%3}, {%4,%5,%6,%7}, {%8,%9}, {%0,%1,%2,%3};\n"
        : "+f"(c[0]), "+f"(c[1]), "+f"(c[2]), "+f"(c[3])
        : "r"(a[0]), "r"(a[1]), "r"(a[2]), "r"(a[3]),
          "r"(b[0]), "r"(b[1]));
}
DEVI void mma16(float c[4], const uint32_t a[4], const uint32_t b[2]) {
    asm("mma.sync.aligned.m16n8k16.row.col.f32.f16.f16.f32 "
        "{%0,%1,%2,%3}, {%4,%5,%6,%7}, {%8,%9}, {%0,%1,%2,%3};\n"
        : "+f"(c[0]), "+f"(c[1]), "+f"(c[2]), "+f"(c[3])
        : "r"(a[0]), "r"(a[1]), "r"(a[2]), "r"(a[3]),
          "r"(b[0]), "r"(b[1]));
}

// ============================================================================
// Stage 3: out[8192,4096] = relu( Hh @ Wnh^T + bn )   (fp16 in, fp32 accum)
// mma.sync m16n8k16. 128x256 CTA tile, 256 threads, 64x64 warp tiles.
// K-tile 128 (8 k-steps), 2-stage cp.async double buffer (204 KB smem).
// ============================================================================
static constexpr int S3_LDH = 136;                  // halves per smem row (272 B)
static constexpr int S3_AS  = 128 * S3_LDH;         // A stage halves
static constexpr int S3_BS  = 256 * S3_LDH;         // B stage halves
static constexpr int S3_STG = S3_AS + S3_BS;        // 52224 halves / stage
static constexpr int S3_SMEM = 2 * S3_STG * (int)sizeof(__half);   // 208896 B

DEVI void s3_fill(__half* st, const __half* __restrict__ A, const __half* __restrict__ B,
                  int bm, int bn, int k0, int tid)
{
    __half* As = st;
    __half* Bs = st + S3_AS;
#pragma unroll
    for (int i = 0; i < 8; ++i) {                   // A: 128 rows x 16 chunks = 2048
        const int ch = tid + (i << 8);
        const int r = ch >> 4, c = ch & 15;
        cp16(smem_u32(As + r * S3_LDH + c * 8),
             A + ((size_t)(bm * 128 + r) << 12) + k0 + (c << 3));
    }
#pragma unroll
    for (int i = 0; i < 16; ++i) {                  // B: 256 rows x 16 chunks = 4096
        const int ch = tid + (i << 8);
        const int r = ch >> 4, c = ch & 15;
        cp16(smem_u32(Bs + r * S3_LDH + c * 8),
             B + ((size_t)(bn * 256 + r) << 12) + k0 + (c << 3));
    }
}

__global__ void __launch_bounds__(256, 1)
gemm3_fp16(const __half* __restrict__ A,    // g_Hh  [8192,4096]
           const __half* __restrict__ B,    // g_Wnh [4096,4096]
           const float* __restrict__ bias,
           float* __restrict__ C)
{
    constexpr int NK = 32;                          // 4096 / 128
    extern __shared__ __half smh[];
    __half* const stg[2] = { smh, smh + S3_STG };

    const int tid  = threadIdx.x;
    const int lane = tid & 31;
    const int wid  = tid >> 5;
    const int g    = lane >> 2;
    const int tig  = lane & 3;
    const int wm   = (wid >> 2) * 64;
    const int wn   = (wid & 3) * 64;
    const int bn = blockIdx.x, bm = blockIdx.y;

    float acc[4][8][4];
#pragma unroll
    for (int mt = 0; mt < 4; ++mt)
#pragma unroll
        for (int nt = 0; nt < 8; ++nt)
#pragma unroll
            for (int i = 0; i < 4; ++i) acc[mt][nt][i] = 0.f;

    s3_fill(stg[0], A, B, bm, bn, 0,   tid); cp_commit();
    s3_fill(stg[1], A, B, bm, bn, 128, tid); cp_commit();

    for (int kt = 0; kt < NK; ++kt) {
        if (kt == NK - 1) cp_wait0(); else cp_wait1();
        __syncthreads();                            // stage kt ready everywhere

        const __half* __restrict__ Ac = stg[kt & 1];
        const __half* __restrict__ Bc = Ac + S3_AS;

#pragma unroll
        for (int ks = 0; ks < 8; ++ks) {
            const int kb = ks * 16 + 2 * tig;
            uint32_t af[4][4];
            uint32_t bf[8][2];
#pragma unroll
            for (int mt = 0; mt < 4; ++mt) {
                const int r0 = (wm + mt * 16 + g) * S3_LDH;
                const int r1 = r0 + 8 * S3_LDH;
                af[mt][0] = *(const uint32_t*)&Ac[r0 + kb];
                af[mt][1] = *(const uint32_t*)&Ac[r1 + kb];
                af[mt][2] = *(const uint32_t*)&Ac[r0 + kb + 8];
                af[mt][3] = *(const uint32_t*)&Ac[r1 + kb + 8];
            }
#pragma unroll
            for (int nt = 0; nt < 8; ++nt) {
                const int rb = (wn + nt * 8 + g) * S3_LDH;
                bf[nt][0] = *(const uint32_t*)&Bc[rb + kb];
                bf[nt][1] = *(const uint32_t*)&Bc[rb + kb + 8];
            }
#pragma unroll
            for (int mt = 0; mt < 4; ++mt)
#pragma unroll
                for (int nt = 0; nt < 8; ++nt)
                    mma16(acc[mt][nt], af[mt], bf[nt]);
        }

        __syncthreads();                            // all warps done with stage kt
        const int nt2 = kt + 2;
        if (nt2 < NK) {
            s3_fill(stg[kt & 1], A, B, bm, bn, nt2 * 128, tid);
            cp_commit();
        }
    }

    // epilogue: bias + relu
#pragma unroll
    for (int mt = 0; mt < 4; ++mt) {
#pragma unroll
        for (int nt = 0; nt < 8; ++nt) {
            const int m = bm * 128 + wm + mt * 16 + g;
            const int n = bn * 256 + wn + nt * 8 + 2 * tig;
            const float2 bb = *(const float2*)(bias + n);
            float2 v0, v1;
            v0.x = fmaxf(acc[mt][nt][0] + bb.x, 0.f);
            v0.y = fmaxf(acc[mt][nt][1] + bb.y, 0.f);
            v1.x = fmaxf(acc[mt][nt][2] + bb.x, 0.f);
            v1.y = fmaxf(acc[mt][nt][3] + bb.y, 0.f);
            *(float2*)(C + ((size_t)m << 12) + n)       = v0;
            *(float2*)(C + ((size_t)(m + 8) << 12) + n) = v1;
        }
    }
}

// ============================================================================
// Stage 2 (specialized K=64, no pipeline): Hh = fp16( V @ Wo^T + bo + x )
// 128x128 CTA tile, 256 threads, 64x32 warp tiles, 2 CTAs/SM.
// ============================================================================
static constexpr int S2_LD   = 68;                  // floats per smem row
static constexpr int S2_SMEM = 2 * 128 * S2_LD * (int)sizeof(float);  // 69632 B

__global__ void __launch_bounds__(256, 2)
gemm2_k64(const float* __restrict__ V,     // [8192,64]
          const float* __restrict__ Wo,    // [4096,64]
          const float* __restrict__ bo,
          const float* __restrict__ x,     // [8192,4096] residual
          __half* __restrict__ Hh)         // [8192,4096] out
{
    extern __shared__ float smf[];
    float* const As = smf;                  // V tile  [128][68]
    float* const Bs = smf + 128 * S2_LD;    // Wo tile [128][68]

    const int tid  = threadIdx.x;
    const int lane = tid & 31;
    const int wid  = tid >> 5;
    const int g    = lane >> 2;
    const int tig  = lane & 3;
    const int wm   = (wid >> 2) * 64;       // 2 warp-rows
    const int wn   = (wid & 3) * 32;        // 4 warp-cols
    const int bn = blockIdx.x, bm = blockIdx.y;

    // load tiles (16 float4 per row, 128 rows each)
#pragma unroll
    for (int i = 0; i < 8; ++i) {
        const int ch = tid + (i << 8);      // 0..2047
        const int r = ch >> 4, c = (ch & 15) << 2;
        float4 t = *(const float4*)(V + (size_t)(bm * 128 + r) * 64 + c);
        t.x = to_tf32(t.x); t.y = to_tf32(t.y); t.z = to_tf32(t.z); t.w = to_tf32(t.w);
        *(float4*)&As[r * S2_LD + c] = t;
    }
#pragma unroll
    for (int i = 0; i < 8; ++i) {
        const int ch = tid + (i << 8);
        const int r = ch >> 4, c = (ch & 15) << 2;
        float4 t = *(const float4*)(Wo + (size_t)(bn * 128 + r) * 64 + c);
        t.x = to_tf32(t.x); t.y = to_tf32(t.y); t.z = to_tf32(t.z); t.w = to_tf32(t.w);
        *(float4*)&Bs[r * S2_LD + c] = t;
    }
    __syncthreads();

    float acc[4][4][4];
#pragma unroll
    for (int mt = 0; mt < 4; ++mt)
#pragma unroll
        for (int nt = 0; nt < 4; ++nt)
#pragma unroll
            for (int i = 0; i < 4; ++i) acc[mt][nt][i] = 0.f;

#pragma unroll
    for (int ks = 0; ks < 8; ++ks) {
        const int c0 = ks * 8 + tig;
        uint32_t af[4][4];
        uint32_t bf[4][2];
#pragma unroll
        for (int mt = 0; mt < 4; ++mt) {
            const int r0 = wm + mt * 16 + g;
            af[mt][0] = __float_as_uint(As[r0 * S2_LD + c0]);
            af[mt][1] = __float_as_uint(As[(r0 + 8) * S2_LD + c0]);
            af[mt][2] = __float_as_uint(As[r0 * S2_LD + c0 + 4]);
            af[mt][3] = __float_as_uint(As[(r0 + 8) * S2_LD + c0 + 4]);
        }
#pragma unroll
        for (int nt = 0; nt < 4; ++nt) {
            const int r0 = wn + nt * 8 + g;
            bf[nt][0] = __float_as_uint(Bs[r0 * S2_LD + c0]);
            bf[nt][1] = __float_as_uint(Bs[r0 * S2_LD + c0 + 4]);
        }
#pragma unroll
        for (int mt = 0; mt < 4; ++mt)
#pragma unroll
            for (int nt = 0; nt < 4; ++nt)
                mma8(acc[mt][nt], af[mt], bf[nt]);
    }

    // epilogue: + bo + x, fp16 out
    __half2* const Ch = (__half2*)Hh;
#pragma unroll
    for (int mt = 0; mt < 4; ++mt) {
#pragma unroll
        for (int nt = 0; nt < 4; ++nt) {
            const int m = bm * 128 + wm + mt * 16 + g;
            const int n = bn * 128 + wn + nt * 8 + 2 * tig;
            const float2 bb = *(const float2*)(bo + n);
            const float2 r0 = *(const float2*)(x + ((size_t)m << 12) + n);
            const float2 r1 = *(const float2*)(x + ((size_t)(m + 8) << 12) + n);
            Ch[(((size_t)m << 12) + n) >> 1] =
                __floats2half2_rn(acc[mt][nt][0] + bb.x + r0.x,
                                  acc[mt][nt][1] + bb.y + r0.y);
            Ch[(((size_t)(m + 8) << 12) + n) >> 1] =
                __floats2half2_rn(acc[mt][nt][2] + bb.x + r1.x,
                                  acc[mt][nt][3] + bb.y + r1.y);
        }
    }
}

// ============================================================================
// fp32 -> fp16 conversion (Wn -> g_Wnh)
// ============================================================================
__global__ void f32_to_f16_kernel(const float2* __restrict__ in, __half2* __restrict__ out, int n2)
{
    for (int i = blockIdx.x * blockDim.x + threadIdx.x; i < n2; i += gridDim.x * blockDim.x) {
        const float2 v = in[i];
        out[i] = __floats2half2_rn(v.x, v.y);
    }
}

// ============================================================================
// V init: V[m][n] = bv[n]  (8192 x 64)
// ============================================================================
__global__ void init_bias_kernel(float4* __restrict__ V, const float4* __restrict__ bv)
{
    for (int i = blockIdx.x * blockDim.x + threadIdx.x; i < 131072; i += gridDim.x * blockDim.x)
        V[i] = bv[i & 15];
}

// ============================================================================
// Stage 1: split-K tf32 GEMM with atomicAdd epilogue (proven)
// ============================================================================
template <int BM, int BN>
__global__ void __launch_bounds__(256, 1)
gemm1_splitk(const float* __restrict__ A,
             const float* __restrict__ B,
             float* __restrict__ C,
             int M, int N, int Klen, int ldk)
{
    constexpr int MT = BM / 32;
    constexpr int NT = BN / 32;
    constexpr int LD = 36;

    extern __shared__ float smemf[];
    float* const As0 = smemf;
    float* const As1 = smemf + BM * LD;
    float* const Bs0 = smemf + 2 * BM * LD;
    float* const Bs1 = smemf + 2 * BM * LD + BN * LD;
    float* const Asb[2] = { As0, As1 };
    float* const Bsb[2] = { Bs0, Bs1 };

    const int tid  = threadIdx.x;
    const int lane = tid & 31;
    const int wid  = tid >> 5;
    const int g    = lane >> 2;
    const int tig  = lane & 3;

    const int wm = (wid >> 2) * (BM / 2);
    const int wn = (wid & 3) * (BN / 4);

    const size_t koff = (size_t)blockIdx.z * Klen;
    const float* Ab = A + (size_t)blockIdx.y * BM * ldk + koff;
    const float* Bb = B + (size_t)blockIdx.x * BN * ldk + koff;

    const int lr = tid >> 3;
    const int lc = (tid & 7) * 4;

    float4 ra[MT], rb[NT];
    float acc[MT][NT][4];
#pragma unroll
    for (int mt = 0; mt < MT; ++mt)
#pragma unroll
        for (int nt = 0; nt < NT; ++nt)
#pragma unroll
            for (int i = 0; i < 4; ++i) acc[mt][nt][i] = 0.f;

    const int ktiles = Klen >> 5;

#pragma unroll
    for (int i = 0; i < MT; ++i)
        ra[i] = *(const float4*)(Ab + (size_t)(lr + 32 * i) * ldk + lc);
#pragma unroll
    for (int i = 0; i < NT; ++i)
        rb[i] = *(const float4*)(Bb + (size_t)(lr + 32 * i) * ldk + lc);
#pragma unroll
    for (int i = 0; i < MT; ++i) {
        float4 t = ra[i];
        t.x = to_tf32(t.x); t.y = to_tf32(t.y); t.z = to_tf32(t.z); t.w = to_tf32(t.w);
        *(float4*)&As0[(lr + 32 * i) * LD + lc] = t;
    }
#pragma unroll
    for (int i = 0; i < NT; ++i) {
        float4 t = rb[i];
        t.x = to_tf32(t.x); t.y = to_tf32(t.y); t.z = to_tf32(t.z); t.w = to_tf32(t.w);
        *(float4*)&Bs0[(lr + 32 * i) * LD + lc] = t;
    }
    __syncthreads();

    for (int kt = 0; kt < ktiles; ++kt) {
        const int cur = kt & 1;
        const bool more = (kt + 1) < ktiles;

        if (more) {
            const int ko = (kt + 1) * 32;
#pragma unroll
            for (int i = 0; i < MT; ++i)
                ra[i] = *(const float4*)(Ab + (size_t)(lr + 32 * i) * ldk + ko + lc);
#pragma unroll
            for (int i = 0; i < NT; ++i)
                rb[i] = *(const float4*)(Bb + (size_t)(lr + 32 * i) * ldk + ko + lc);
        }

        const float* __restrict__ Ac = Asb[cur];
        const float* __restrict__ Bc = Bsb[cur];
#pragma unroll
        for (int ks = 0; ks < 4; ++ks) {
            uint32_t af[MT][4];
            uint32_t bf[NT][2];
            const int c0 = ks * 8 + tig;
#pragma unroll
            for (int mt = 0; mt < MT; ++mt) {
                const int r0 = wm + mt * 16 + g;
                af[mt][0] = __float_as_uint(Ac[r0 * LD + c0]);
                af[mt][1] = __float_as_uint(Ac[(r0 + 8) * LD + c0]);
                af[mt][2] = __float_as_uint(Ac[r0 * LD + c0 + 4]);
                af[mt][3] = __float_as_uint(Ac[(r0 + 8) * LD + c0 + 4]);
            }
#pragma unroll
            for (int nt = 0; nt < NT; ++nt) {
                const int r0 = wn + nt * 8 + g;
                bf[nt][0] = __float_as_uint(Bc[r0 * LD + c0]);
                bf[nt][1] = __float_as_uint(Bc[r0 * LD + c0 + 4]);
            }
#pragma unroll
            for (int mt = 0; mt < MT; ++mt)
#pragma unroll
                for (int nt = 0; nt < NT; ++nt)
                    mma8(acc[mt][nt], af[mt], bf[nt]);
        }

        if (more) {
            float* const An = Asb[cur ^ 1];
            float* const Bn = Bsb[cur ^ 1];
#pragma unroll
            for (int i = 0; i < MT; ++i) {
                float4 t = ra[i];
                t.x = to_tf32(t.x); t.y = to_tf32(t.y); t.z = to_tf32(t.z); t.w = to_tf32(t.w);
                *(float4*)&An[(lr + 32 * i) * LD + lc] = t;
            }
#pragma unroll
            for (int i = 0; i < NT; ++i) {
                float4 t = rb[i];
                t.x = to_tf32(t.x); t.y = to_tf32(t.y); t.z = to_tf32(t.z); t.w = to_tf32(t.w);
                *(float4*)&Bn[(lr + 32 * i) * LD + lc] = t;
            }
        }
        __syncthreads();
    }

    const int m0 = blockIdx.y * BM + wm;
    const int n0 = blockIdx.x * BN + wn;
#pragma unroll
    for (int mt = 0; mt < MT; ++mt) {
#pragma unroll
        for (int nt = 0; nt < NT; ++nt) {
            const int m = m0 + mt * 16 + g;
            const int n = n0 + nt * 8 + 2 * tig;
            atomicAdd(C + (size_t)m * N + n,           acc[mt][nt][0]);
            atomicAdd(C + (size_t)m * N + n + 1,       acc[mt][nt][1]);
            atomicAdd(C + (size_t)(m + 8) * N + n,     acc[mt][nt][2]);
            atomicAdd(C + (size_t)(m + 8) * N + n + 1, acc[mt][nt][3]);
        }
    }
}

// ============================================================================
// launch
// Inputs (metadata order): x, Wq, bq, Wk, bk, Wv, bv, Wo, bo, Wn, bn
// Singleton softmax => attended == v; Wq/bq/Wk/bk dead.
// ============================================================================
extern "C" void kernel_launch(void* const* d_in, const int* in_sizes, int n_in,
                              void* d_out, int out_size)
{
    const float* x  = (const float*)d_in[0];
    const float* Wv = (const float*)d_in[5];
    const float* bv = (const float*)d_in[6];
    const float* Wo = (const float*)d_in[7];
    const float* bo = (const float*)d_in[8];
    const float* Wn = (const float*)d_in[9];
    const float* bn = (const float*)d_in[10];
    float* out = (float*)d_out;

    float  *V = nullptr;
    __half *Hh = nullptr, *Wnh = nullptr;
    cudaGetSymbolAddress((void**)&V,   g_V);
    cudaGetSymbolAddress((void**)&Hh,  g_Hh);
    cudaGetSymbolAddress((void**)&Wnh, g_Wnh);

    constexpr int SM64 = 2 * (64 + 64) * 36 * (int)sizeof(float);

    cudaFuncSetAttribute(gemm1_splitk<64, 64>,
                         cudaFuncAttributeMaxDynamicSharedMemorySize, SM64);
    cudaFuncSetAttribute(gemm2_k64,
                         cudaFuncAttributeMaxDynamicSharedMemorySize, S2_SMEM);
    cudaFuncSetAttribute(gemm3_fp16,
                         cudaFuncAttributeMaxDynamicSharedMemorySize, S3_SMEM);

    // Wn -> fp16 copy
    f32_to_f16_kernel<<<4096, 256>>>((const float2*)Wn, (__half2*)Wnh, 4096 * 4096 / 2);

    // Stage 1: V = bv ; V += x @ Wv^T  (split-K x4, atomicAdd)
    init_bias_kernel<<<512, 256>>>((float4*)V, (const float4*)bv);
    gemm1_splitk<64, 64><<<dim3(1, 128, 4), 256, SM64>>>(
        x, Wv, V, 8192, 64, 1024, 4096);

    // Stage 2: Hh = fp16( V @ Wo^T + bo + x )  — specialized K=64, 2 CTAs/SM
    gemm2_k64<<<dim3(32, 64), 256, S2_SMEM>>>(V, Wo, bo, x, Hh);

    // Stage 3: out = relu(Hh @ Wnh^T + bn) — K-tile 128, 2-stage double buffer
    gemm3_fp16<<<dim3(16, 64), 256, S3_SMEM>>>(Hh, Wnh, bn, out);
}